// round 10
// baseline (speedup 1.0000x reference)
#include <cuda_runtime.h>
#include <cstdint>

// ---------------------------------------------------------------------------
// Skeletonize — single persistent fused kernel.
//   padded grid: (2,162,162,162); bit-packed along z: 3 x u64 per (b,X,Y) row
//   RNG: JAX threefry_partitionable: counter (0, flat_index), bits = o0 ^ o1
//   Global sync: software barrier (all 154 blocks co-resident by construction)
// ---------------------------------------------------------------------------

#define NPAD 162
#define ROWS_PER_BATCH (162*162)        // 26244
#define NROWS (2*ROWS_PER_BATCH)        // 52488
#define WPR 3
#define HALF 4251528u                   // 162^3
#define NBLK 154
#define NTHR 256
#define TOTTHR (NBLK*NTHR)              // 39424

typedef unsigned long long u64;

__device__ u64 g_img[NROWS*WPR];
__device__ u64 g_end[NROWS*WPR];
__device__ unsigned g_count = 0;
__device__ unsigned g_gen   = 0;

// ---------------- global barrier (persistent-safe, replay-safe) -------------
__device__ __forceinline__ void gsync(){
  __syncthreads();
  if (threadIdx.x == 0){
    __threadfence();
    unsigned gen = *((volatile unsigned*)&g_gen);
    if (atomicAdd(&g_count, 1u) == NBLK - 1u){
      atomicExch(&g_count, 0u);
      __threadfence();
      *((volatile unsigned*)&g_gen) = gen + 1u;
    } else {
      while (*((volatile unsigned*)&g_gen) == gen) __nanosleep(32);
    }
    __threadfence();
  }
  __syncthreads();
}

// ---------------- RNG ----------------
__device__ __forceinline__ uint32_t rotl32(uint32_t x, int r){ return (x<<r)|(x>>(32-r)); }

__device__ __forceinline__ uint32_t threefry_xor(uint32_t x0, uint32_t x1){
  const uint32_t ks1 = 42u;
  const uint32_t ks2 = 0x1BD11BDAu ^ 42u;
  x0 += 0u; x1 += ks1;
#define TF_RND(r) { x0 += x1; x1 = rotl32(x1, (r)); x1 ^= x0; }
  TF_RND(13) TF_RND(15) TF_RND(26) TF_RND(6)
  x0 += ks1; x1 += ks2 + 1u;
  TF_RND(17) TF_RND(29) TF_RND(16) TF_RND(24)
  x0 += ks2; x1 += 2u;
  TF_RND(13) TF_RND(15) TF_RND(26) TF_RND(6)
  x0 += 0u;  x1 += ks1 + 3u;
  TF_RND(17) TF_RND(29) TF_RND(16) TF_RND(24)
  x0 += ks1; x1 += ks2 + 4u;
  TF_RND(13) TF_RND(15) TF_RND(26) TF_RND(6)
  x0 += ks2; x1 += 5u;
#undef TF_RND
  return x0 ^ x1;
}

__device__ __forceinline__ int hard_bit(uint32_t bits, float img){
  float f = __fadd_rn(__uint_as_float((bits >> 9) | 0x3f800000u), -1.0f);
  float u = __fadd_rn(__fmul_rn(f, 1.0f), 1e-8f);
  u = fmaxf(1e-8f, u);
  float noise = __fadd_rn(logf(u), -log1pf(-u));
  float alpha = __fdiv_rn(__fadd_rn(img, 1e-8f),
                          __fadd_rn(__fadd_rn(1.0f, -img), 1e-8f));
  float zv = __fadd_rn(logf(alpha), __fmul_rn(noise, 0.33f));
  return zv > 0.0f;
}

// ---------------- pass bodies ----------------
#define SAT(one, ge, x) { u64 _x=(x); (ge) |= (one) & _x; (one) |= _x; }

__device__ __forceinline__ void endpoint_body(int t){
  int w = t % 3; int r = t / 3;
  int Y = r % NPAD; int rX = r / NPAD; int X = rX % NPAD; int b = rX / NPAD;
  u64 one=0, ge=0;
  #pragma unroll
  for (int i=0;i<3;i++){
    #pragma unroll
    for (int j=0;j<3;j++){
      int XX = X + i - 1, YY = Y + j - 1;
      bool ok = (XX>=0 && XX<NPAD && YY>=0 && YY<NPAD);
      const u64* row = g_img + (size_t)((b*NPAD + XX)*NPAD + YY)*WPR;
      u64 wm = (ok && w>0) ? __ldcg(row + (w-1)) : 0ull;
      u64 wc =  ok         ? __ldcg(row + w)     : 0ull;
      u64 wp = (ok && w<2) ? __ldcg(row + (w+1)) : 0ull;
      u64 M = (wc<<1) | (wm>>63);
      u64 P = (wc>>1) | (wp<<63);
      SAT(one, ge, M);
      if (!(i==1 && j==1)) SAT(one, ge, wc);
      SAT(one, ge, P);
    }
  }
  g_end[t] = ~ge;           // bit=1 <=> n26 <= 1
}

__device__ __forceinline__ void simple_body(int t, int xo, int yo, int zo){
  int w = t % 3; int q = t/3;
  int Yi = q % 81; q /= 81;
  int Xi = q % 81; int b = q / 81;
  int X = xo + 2*Xi, Y = yo + 2*Yi;

  u64 A[3][3][3];
  #pragma unroll
  for (int i=0;i<3;i++){
    #pragma unroll
    for (int j=0;j<3;j++){
      int XX = X + i - 1, YY = Y + j - 1;
      bool ok = (XX>=0 && XX<NPAD && YY>=0 && YY<NPAD);
      const u64* row = g_img + (size_t)((b*NPAD + XX)*NPAD + YY)*WPR;
      u64 wm = (ok && w>0) ? __ldcg(row + (w-1)) : 0ull;
      u64 wc =  ok         ? __ldcg(row + w)     : 0ull;
      u64 wp = (ok && w<2) ? __ldcg(row + (w+1)) : 0ull;
      A[i][j][0] = (wc<<1) | (wm>>63);
      A[i][j][1] = wc;
      A[i][j][2] = (wc>>1) | (wp<<63);
    }
  }

  u64 one18=0, ge18=0;
  #pragma unroll
  for (int i=0;i<3;i++){
    #pragma unroll
    for (int j=0;j<3;j++){
      #pragma unroll
      for (int k=0;k<3;k++){
        int c = (i==1?0:1)+(j==1?0:1)+(k==1?0:1);
        if (c==1 || c==2) SAT(one18, ge18, A[i][j][k]);
      }
    }
  }
  u64 one26=one18, ge26=ge18;
  #pragma unroll
  for (int i=0;i<3;i+=2){
    #pragma unroll
    for (int j=0;j<3;j+=2){
      #pragma unroll
      for (int k=0;k<3;k+=2) SAT(one26, ge26, A[i][j][k]);
    }
  }
  u64 one6=0, ge6=0;
  SAT(one6, ge6, ~A[0][1][1]); SAT(one6, ge6, ~A[2][1][1]);
  SAT(one6, ge6, ~A[1][0][1]); SAT(one6, ge6, ~A[1][2][1]);
  SAT(one6, ge6, ~A[1][1][0]); SAT(one6, ge6, ~A[1][1][2]);

  u64 anyB = 0;
  #pragma unroll
  for (int i=0;i<3;i+=2){
    #pragma unroll
    for (int j=0;j<3;j+=2){
      #pragma unroll
      for (int k=0;k<3;k+=2){
        u64 others = A[i][1][1] | A[1][j][1] | A[1][1][k]
                   | A[i][j][1] | A[i][1][k] | A[1][j][k];
        anyB |= A[i][j][k] & ~others;
      }
    }
  }
  u64 anyA = 0;
  #pragma unroll
  for (int s=0;s<3;s+=2){
    anyA |= ~A[s][1][1] & A[s][0][1] & A[s][2][1] & A[s][1][0] & A[s][1][2];
    anyA |= ~A[1][s][1] & A[0][s][1] & A[2][s][1] & A[1][s][0] & A[1][s][2];
    anyA |= ~A[1][1][s] & A[0][1][s] & A[2][1][s] & A[1][0][s] & A[1][2][s];
  }

  u64 notB = ~anyB;
  u64 simple = (one6 & ~ge6)
             | (one26 & ~ge26)
             | (one18 & ~ge18 & notB)
             | (ge6 & ~anyA & notB);
  u64 zmask = (zo==0) ? 0x5555555555555555ull : 0xAAAAAAAAAAAAAAAAull;
  size_t idx = (size_t)((b*NPAD + X)*NPAD + Y)*WPR + w;
  u64 del = simple & ~__ldcg(g_end + idx) & zmask;
  if (del){
    g_img[idx] = __ldcg(g_img + idx) & ~del;
  }
}

// ---------------- fused persistent kernel ----------------
__global__ void __launch_bounds__(NTHR, 2)
k_fused(const float* __restrict__ in, float* __restrict__ out){
  const int gt   = blockIdx.x*NTHR + threadIdx.x;
  const int lane = gt & 31;
  const int wgid = gt >> 5;
  const int nwarps = TOTTHR >> 5;       // 1232

  // ---- phase 1: binarize (warp-ballot packing) ----
  for (int u = wgid; u < ROWS_PER_BATCH*6; u += nwarps){
    int r0 = u / 6, k = u % 6;
    int X = r0 / NPAD, Y = r0 % NPAD;
    int z = k*32 + lane;
    bool valid = (z < NPAD);
    uint32_t i = (uint32_t)r0 * (uint32_t)NPAD + (uint32_t)(valid ? z : 0);
    uint32_t b0bits = threefry_xor(0u, i);
    uint32_t b1bits = threefry_xor(0u, i + HALF);
    bool interior = valid && X>=1 && X<=160 && Y>=1 && Y<=160 && z>=1 && z<=160;
    float v0 = 0.f, v1 = 0.f;
    if (interior){
      int ui = ((X-1)*160 + (Y-1))*160 + (z-1);
      v0 = __ldg(in + ui);
      v1 = __ldg(in + ui + 160*160*160);
    }
    int h0 = hard_bit(b0bits, v0);
    int h1 = hard_bit(b1bits, v1);
    uint32_t m0 = __ballot_sync(0xFFFFFFFFu, valid && h0);
    uint32_t m1 = __ballot_sync(0xFFFFFFFFu, valid && h1);
    if (lane == 0){
      uint32_t* p = (uint32_t*)g_img;
      p[(size_t)r0*6 + k] = m0;
      p[(size_t)(ROWS_PER_BATCH + r0)*6 + k] = m1;
    }
  }
  gsync();

  // ---- phase 2: 5 iterations x (endpoint + 8 parity sub-passes) ----
  const int offs[8][3] = {{0,0,0},{1,0,0},{0,1,0},{1,1,0},
                          {0,0,1},{1,0,1},{0,1,1},{1,1,1}};
  for (int it = 0; it < 5; ++it){
    for (int t = gt; t < NROWS*WPR; t += TOTTHR) endpoint_body(t);
    gsync();
    #pragma unroll 1
    for (int o = 0; o < 8; ++o){
      if (gt < 2*81*81*3) simple_body(gt, offs[o][0], offs[o][1], offs[o][2]);
      gsync();
    }
  }

  // ---- phase 3: unpack (row per thread, float4 stores) ----
  for (int r = gt; r < 2*160*160; r += TOTTHR){
    int y = r % 160; int q = r / 160;
    int x = q % 160; int b = q / 160;
    size_t row = (size_t)((b*NPAD + (x+1))*NPAD + (y+1))*WPR;
    u64 w0 = __ldcg(g_img + row);
    u64 w1 = __ldcg(g_img + row + 1);
    u64 w2 = __ldcg(g_img + row + 2);
    // shift right by 1: bit z of a* corresponds to padded zz = z+1
    u64 a0 = (w0>>1) | (w1<<63);
    u64 a1 = (w1>>1) | (w2<<63);
    u64 a2 = (w2>>1);
    float4* o4 = (float4*)(out + (size_t)r*160);
    #pragma unroll
    for (int k = 0; k < 16; k++){
      unsigned nib = (unsigned)((a0 >> (4*k)) & 15ull);
      o4[k] = make_float4((float)(nib&1), (float)((nib>>1)&1),
                          (float)((nib>>2)&1), (float)((nib>>3)&1));
    }
    #pragma unroll
    for (int k = 0; k < 16; k++){
      unsigned nib = (unsigned)((a1 >> (4*k)) & 15ull);
      o4[16+k] = make_float4((float)(nib&1), (float)((nib>>1)&1),
                             (float)((nib>>2)&1), (float)((nib>>3)&1));
    }
    #pragma unroll
    for (int k = 0; k < 8; k++){
      unsigned nib = (unsigned)((a2 >> (4*k)) & 15ull);
      o4[32+k] = make_float4((float)(nib&1), (float)((nib>>1)&1),
                             (float)((nib>>2)&1), (float)((nib>>3)&1));
    }
  }
}

extern "C" void kernel_launch(void* const* d_in, const int* in_sizes, int n_in,
                              void* d_out, int out_size){
  const float* in = (const float*)d_in[0];
  float* out = (float*)d_out;
  (void)in_sizes; (void)n_in; (void)out_size;
  k_fused<<<NBLK, NTHR>>>(in, out);
}

// round 11
// speedup vs baseline: 1.2858x; 1.2858x over previous
#include <cuda_runtime.h>
#include <cstdint>

// ---------------------------------------------------------------------------
// Skeletonize — bit-packed, smem-tiled thinning passes.
//   padded grid: (2,162,162,162); bit-packed along z: 3 x u64 per (b,X,Y) row
//   RNG: JAX threefry_partitionable: counter (0, flat_index), bits = o0 ^ o1
// ---------------------------------------------------------------------------

#define NPAD 162
#define ROWS_PER_BATCH (162*162)        // 26244
#define NROWS (2*ROWS_PER_BATCH)        // 52488
#define WPR 3
#define HALF 4251528u                   // 162^3

typedef unsigned long long u64;

__device__ u64 g_img[NROWS*WPR];
__device__ u64 g_end[NROWS*WPR];

__device__ __forceinline__ uint32_t rotl32(uint32_t x, int r){ return (x<<r)|(x>>(32-r)); }

// JAX threefry2x32, key (0,42), partitionable combine
__device__ __forceinline__ uint32_t threefry_xor(uint32_t x0, uint32_t x1){
  const uint32_t ks1 = 42u;
  const uint32_t ks2 = 0x1BD11BDAu ^ 42u;
  x0 += 0u; x1 += ks1;
#define TF_RND(r) { x0 += x1; x1 = rotl32(x1, (r)); x1 ^= x0; }
  TF_RND(13) TF_RND(15) TF_RND(26) TF_RND(6)
  x0 += ks1; x1 += ks2 + 1u;
  TF_RND(17) TF_RND(29) TF_RND(16) TF_RND(24)
  x0 += ks2; x1 += 2u;
  TF_RND(13) TF_RND(15) TF_RND(26) TF_RND(6)
  x0 += 0u;  x1 += ks1 + 3u;
  TF_RND(17) TF_RND(29) TF_RND(16) TF_RND(24)
  x0 += ks1; x1 += ks2 + 4u;
  TF_RND(13) TF_RND(15) TF_RND(26) TF_RND(6)
  x0 += ks2; x1 += 5u;
#undef TF_RND
  return x0 ^ x1;
}

__device__ __forceinline__ int hard_bit(uint32_t bits, float img){
  float f = __fadd_rn(__uint_as_float((bits >> 9) | 0x3f800000u), -1.0f);
  float u = __fadd_rn(__fmul_rn(f, 1.0f), 1e-8f);
  u = fmaxf(1e-8f, u);
  float noise = __fadd_rn(logf(u), -log1pf(-u));
  float alpha = __fdiv_rn(__fadd_rn(img, 1e-8f),
                          __fadd_rn(__fadd_rn(1.0f, -img), 1e-8f));
  float zv = __fadd_rn(logf(alpha), __fmul_rn(noise, 0.33f));
  return zv > 0.0f;
}

__global__ void k_binarize(const float* __restrict__ in){
  int gt = blockIdx.x*blockDim.x + threadIdx.x;
  int W = gt >> 5;
  int lane = gt & 31;
  if (W >= ROWS_PER_BATCH*6) return;
  int r0 = W / 6, k = W % 6;
  int X = r0 / NPAD, Y = r0 % NPAD;
  int z = k*32 + lane;
  bool valid = (z < NPAD);
  uint32_t i = (uint32_t)r0 * (uint32_t)NPAD + (uint32_t)(valid ? z : 0);
  uint32_t b0bits = threefry_xor(0u, i);
  uint32_t b1bits = threefry_xor(0u, i + HALF);
  bool interior = valid && X>=1 && X<=160 && Y>=1 && Y<=160 && z>=1 && z<=160;
  float v0 = 0.f, v1 = 0.f;
  if (interior){
    int ui = ((X-1)*160 + (Y-1))*160 + (z-1);
    v0 = in[ui];
    v1 = in[ui + 160*160*160];
  }
  int h0 = hard_bit(b0bits, v0);
  int h1 = hard_bit(b1bits, v1);
  uint32_t m0 = __ballot_sync(0xFFFFFFFFu, valid && h0);
  uint32_t m1 = __ballot_sync(0xFFFFFFFFu, valid && h1);
  if (lane == 0){
    uint32_t* p = (uint32_t*)g_img;
    p[(size_t)r0*6 + k] = m0;
    p[(size_t)(ROWS_PER_BATCH + r0)*6 + k] = m1;
  }
}

#define SAT(one, ge, x) { u64 _x=(x); (ge) |= (one) & _x; (one) |= _x; }

// ---- slab loader: rows XX in {X-1,X,X+1}, all YY, all 3 words -> smem ----
__device__ __forceinline__ void load_slab(u64 (*S)[NPAD][3], int b, int X, int nthr){
  for (int idx = threadIdx.x; idx < 3*NPAD*3; idx += nthr){
    int i = idx / (NPAD*3); int rem = idx % (NPAD*3);
    int YY = rem / 3, w = rem % 3;
    int XX = X + i - 1;
    S[i][YY][w] = (XX >= 0 && XX < NPAD)
        ? g_img[(size_t)((b*NPAD + XX)*NPAD + YY)*WPR + w] : 0ull;
  }
}

// ---- endpoint: one block per (b, X); thread -> (Y, w) ----
__global__ void __launch_bounds__(512) k_endpoint_t(){
  __shared__ u64 S[3][NPAD][3];
  int blk = blockIdx.x;               // 0..323
  int X = blk % NPAD; int b = blk / NPAD;
  load_slab(S, b, X, 512);
  __syncthreads();
  int tid = threadIdx.x;
  if (tid >= NPAD*3) return;
  int Y = tid / 3, w = tid % 3;
  u64 one=0, ge=0;
  #pragma unroll
  for (int i=0;i<3;i++){
    #pragma unroll
    for (int j=0;j<3;j++){
      int YY = Y + j - 1;
      bool ok = (YY >= 0 && YY < NPAD);
      u64 wm = (ok && w>0) ? S[i][YY][w-1] : 0ull;
      u64 wc =  ok         ? S[i][YY][w]   : 0ull;
      u64 wp = (ok && w<2) ? S[i][YY][w+1] : 0ull;
      u64 M = (wc<<1) | (wm>>63);
      u64 P = (wc>>1) | (wp<<63);
      SAT(one, ge, M);
      if (!(i==1 && j==1)) SAT(one, ge, wc);
      SAT(one, ge, P);
    }
  }
  g_end[(size_t)((b*NPAD + X)*NPAD + Y)*WPR + w] = ~ge;
}

// ---- simple sub-pass: one block per (b, Xi); thread -> (Yi, w) ----
__global__ void __launch_bounds__(256) k_simple_t(int xo, int yo, int zo){
  __shared__ u64 S[3][NPAD][3];
  int blk = blockIdx.x;               // 0..161
  int Xi = blk % 81; int b = blk / 81;
  int X = xo + 2*Xi;
  load_slab(S, b, X, 256);
  __syncthreads();
  int tid = threadIdx.x;
  if (tid >= 81*3) return;
  int Yi = tid / 3, w = tid % 3;
  int Y = yo + 2*Yi;

  u64 A[3][3][3];
  #pragma unroll
  for (int i=0;i<3;i++){
    #pragma unroll
    for (int j=0;j<3;j++){
      int YY = Y + j - 1;
      bool ok = (YY >= 0 && YY < NPAD);
      u64 wm = (ok && w>0) ? S[i][YY][w-1] : 0ull;
      u64 wc =  ok         ? S[i][YY][w]   : 0ull;
      u64 wp = (ok && w<2) ? S[i][YY][w+1] : 0ull;
      A[i][j][0] = (wc<<1) | (wm>>63);
      A[i][j][1] = wc;
      A[i][j][2] = (wc>>1) | (wp<<63);
    }
  }

  u64 one18=0, ge18=0;
  #pragma unroll
  for (int i=0;i<3;i++){
    #pragma unroll
    for (int j=0;j<3;j++){
      #pragma unroll
      for (int k=0;k<3;k++){
        int c = (i==1?0:1)+(j==1?0:1)+(k==1?0:1);
        if (c==1 || c==2) SAT(one18, ge18, A[i][j][k]);
      }
    }
  }
  u64 one26=one18, ge26=ge18;
  #pragma unroll
  for (int i=0;i<3;i+=2){
    #pragma unroll
    for (int j=0;j<3;j+=2){
      #pragma unroll
      for (int k=0;k<3;k+=2) SAT(one26, ge26, A[i][j][k]);
    }
  }
  u64 one6=0, ge6=0;
  SAT(one6, ge6, ~A[0][1][1]); SAT(one6, ge6, ~A[2][1][1]);
  SAT(one6, ge6, ~A[1][0][1]); SAT(one6, ge6, ~A[1][2][1]);
  SAT(one6, ge6, ~A[1][1][0]); SAT(one6, ge6, ~A[1][1][2]);

  u64 anyB = 0;
  #pragma unroll
  for (int i=0;i<3;i+=2){
    #pragma unroll
    for (int j=0;j<3;j+=2){
      #pragma unroll
      for (int k=0;k<3;k+=2){
        u64 others = A[i][1][1] | A[1][j][1] | A[1][1][k]
                   | A[i][j][1] | A[i][1][k] | A[1][j][k];
        anyB |= A[i][j][k] & ~others;
      }
    }
  }
  u64 anyA = 0;
  #pragma unroll
  for (int s=0;s<3;s+=2){
    anyA |= ~A[s][1][1] & A[s][0][1] & A[s][2][1] & A[s][1][0] & A[s][1][2];
    anyA |= ~A[1][s][1] & A[0][s][1] & A[2][s][1] & A[1][s][0] & A[1][s][2];
    anyA |= ~A[1][1][s] & A[0][1][s] & A[2][1][s] & A[1][0][s] & A[1][2][s];
  }

  u64 notB = ~anyB;
  u64 simple = (one6 & ~ge6)
             | (one26 & ~ge26)
             | (one18 & ~ge18 & notB)
             | (ge6 & ~anyA & notB);
  u64 zmask = (zo==0) ? 0x5555555555555555ull : 0xAAAAAAAAAAAAAAAAull;
  size_t idx = (size_t)((b*NPAD + X)*NPAD + Y)*WPR + w;
  u64 del = simple & ~g_end[idx] & zmask;
  if (del) g_img[idx] &= ~del;
}

__global__ void k_unpack(float* __restrict__ out){
  int t = blockIdx.x*blockDim.x + threadIdx.x;
  if (t >= 2*160*160*160) return;
  int z = t % 160; int q = t/160;
  int y = q % 160; q /= 160;
  int x = q % 160; int b = q / 160;
  int zz = z + 1;
  size_t row = (size_t)((b*NPAD + (x+1))*NPAD + (y+1));
  u64 wv = g_img[row*WPR + (zz>>6)];
  out[t] = (float)((wv >> (zz & 63)) & 1ull);
}

extern "C" void kernel_launch(void* const* d_in, const int* in_sizes, int n_in,
                              void* d_out, int out_size){
  const float* in = (const float*)d_in[0];
  float* out = (float*)d_out;
  (void)in_sizes; (void)n_in; (void)out_size;

  k_binarize<<<19683, 256>>>(in);

  static const int OFF[8][3] = {{0,0,0},{1,0,0},{0,1,0},{1,1,0},
                                {0,0,1},{1,0,1},{0,1,1},{1,1,1}};
  for (int it = 0; it < 5; ++it){
    k_endpoint_t<<<2*NPAD, 512>>>();
    for (int o = 0; o < 8; ++o)
      k_simple_t<<<2*81, 256>>>(OFF[o][0], OFF[o][1], OFF[o][2]);
  }

  k_unpack<<<(2*160*160*160 + 255)/256, 256>>>(out);
}